// round 1
// baseline (speedup 1.0000x reference)
#include <cuda_runtime.h>
#include <cuda_bf16.h>
#include <cstdint>

#define D_MODEL 1024
#define N_EXP   8
#define N_TOK   8192          // 4 * 2048
#define CAP     8192          // worst-case tokens per expert

// ---------------- device scratch (no allocation allowed) ----------------
__device__ int   g_cnt[N_EXP];
__device__ int   g_tok[N_EXP * CAP];
__device__ float g_wgt[N_EXP * CAP];
__device__ float g_H[(size_t)N_EXP * CAP * D_MODEL];   // 256 MB hidden scratch

// ---------------- helpers ----------------
__device__ __forceinline__ unsigned f2tf32(float f) {
    unsigned r;
    asm("cvt.rna.tf32.f32 %0, %1;" : "=r"(r) : "f"(f));
    return r;
}

__device__ __forceinline__ void mma_tf32(float* c, const unsigned* a, const unsigned* b) {
    asm volatile(
        "mma.sync.aligned.m16n8k8.row.col.f32.tf32.tf32.f32 "
        "{%0,%1,%2,%3}, {%4,%5,%6,%7}, {%8,%9}, {%0,%1,%2,%3};"
        : "+f"(c[0]), "+f"(c[1]), "+f"(c[2]), "+f"(c[3])
        : "r"(a[0]), "r"(a[1]), "r"(a[2]), "r"(a[3]),
          "r"(b[0]), "r"(b[1]));
}

// ---------------- kernel 0: reset counters ----------------
__global__ void zero_cnt_kernel() {
    if (threadIdx.x < N_EXP) g_cnt[threadIdx.x] = 0;
}

// ---------------- kernel 1: gating + top-2 + assignment build ----------------
__global__ void gate_kernel(const float* __restrict__ x,
                            const float* __restrict__ Wg,
                            const float* __restrict__ bg) {
    int tok  = blockIdx.x * 8 + (threadIdx.x >> 5);
    int lane = threadIdx.x & 31;
    if (tok >= N_TOK) return;
    const float* xr = x + (size_t)tok * D_MODEL;

    float s[8];
#pragma unroll
    for (int e = 0; e < 8; e++) s[e] = 0.f;

    for (int k = lane; k < D_MODEL; k += 32) {
        float xv = xr[k];
        const float4* wr = (const float4*)(Wg + (size_t)k * N_EXP);
        float4 w0 = wr[0], w1 = wr[1];
        s[0] += xv * w0.x; s[1] += xv * w0.y; s[2] += xv * w0.z; s[3] += xv * w0.w;
        s[4] += xv * w1.x; s[5] += xv * w1.y; s[6] += xv * w1.z; s[7] += xv * w1.w;
    }
#pragma unroll
    for (int e = 0; e < 8; e++)
#pragma unroll
        for (int off = 16; off > 0; off >>= 1)
            s[e] += __shfl_xor_sync(0xffffffffu, s[e], off);

    if (lane == 0) {
        float best = -3.4e38f, best2 = -3.4e38f;
        int e0 = 0, e1 = 0;
#pragma unroll
        for (int e = 0; e < 8; e++) {
            float v = s[e] + bg[e];
            if (v > best)       { best2 = best; e1 = e0; best = v; e0 = e; }
            else if (v > best2) { best2 = v; e1 = e; }
        }
        int p0 = atomicAdd(&g_cnt[e0], 1);
        g_tok[e0 * CAP + p0] = tok;
        g_wgt[e0 * CAP + p0] = best;
        int p1 = atomicAdd(&g_cnt[e1], 1);
        g_tok[e1 * CAP + p1] = tok;
        g_wgt[e1 * CAP + p1] = best2;
    }
}

// ---------------- kernels 2/3: grouped expert GEMM ----------------
// FIRST = true : H = relu(X_gathered @ W1[e] + b1[e])    (rows gathered via g_tok)
// FIRST = false: out[tok] += w * (H @ W2[e] + b2[e])     (atomic accumulate)
//
// Block tile 128x128x32, 256 threads, 8 warps in 2(m) x 4(n) layout (64x32 each).
template <bool FIRST>
__global__ void __launch_bounds__(256)
moe_gemm_kernel(const float* __restrict__ X,
                const float* __restrict__ W,     // [8][1024][1024]
                const float* __restrict__ bias,  // [8][1024]
                float* __restrict__ out) {
    const int e   = blockIdx.z;
    const int cnt = g_cnt[e];
    const int m0  = blockIdx.y * 128;
    if (m0 >= cnt) return;
    const int n0  = blockIdx.x * 128;
    const float* Wb = W + (size_t)e * D_MODEL * D_MODEL;

    __shared__ unsigned As[128][36];   // [row][k], pad 4 -> conflict-free frag reads
    __shared__ unsigned Bs[32][136];   // [k][n],  pad 8 -> conflict-free frag reads

    const int tid  = threadIdx.x;
    const int lane = tid & 31;
    const int warp = tid >> 5;
    const int wm   = (warp >> 2) * 64;   // warp m base within block tile
    const int wn   = (warp & 3) * 32;    // warp n base within block tile
    const int g    = lane >> 2;          // groupID (0..7)
    const int tg   = lane & 3;           // thread in group (0..3)

    // A-load assignment: 2 threads per row, 4 float4 each
    const int arow  = tid >> 1;
    const int acol0 = (tid & 1) * 16;
    const float* a_src;
    if (FIRST) {
        int a_idx = m0 + arow;
        int tok   = (a_idx < cnt) ? g_tok[e * CAP + a_idx] : 0;
        a_src = X + (size_t)tok * D_MODEL;
    } else {
        a_src = g_H + ((size_t)e * CAP + (size_t)(m0 + arow)) * D_MODEL;
    }

    float c[16][4];
#pragma unroll
    for (int i = 0; i < 16; i++)
#pragma unroll
        for (int j = 0; j < 4; j++) c[i][j] = 0.f;

    for (int kt = 0; kt < D_MODEL; kt += 32) {
        // ---- global -> shared (with tf32 rounding) ----
#pragma unroll
        for (int i = 0; i < 4; i++) {
            float4 v = *(const float4*)(a_src + kt + acol0 + i * 4);
            int cb = acol0 + i * 4;
            As[arow][cb + 0] = f2tf32(v.x);
            As[arow][cb + 1] = f2tf32(v.y);
            As[arow][cb + 2] = f2tf32(v.z);
            As[arow][cb + 3] = f2tf32(v.w);
        }
#pragma unroll
        for (int i = 0; i < 4; i++) {
            int f4 = tid + i * 256;
            int bk = f4 >> 5;
            int bc = (f4 & 31) * 4;
            float4 v = *(const float4*)(Wb + (size_t)(kt + bk) * D_MODEL + n0 + bc);
            Bs[bk][bc + 0] = f2tf32(v.x);
            Bs[bk][bc + 1] = f2tf32(v.y);
            Bs[bk][bc + 2] = f2tf32(v.z);
            Bs[bk][bc + 3] = f2tf32(v.w);
        }
        __syncthreads();

        // ---- mma over 4 k-steps of 8 ----
#pragma unroll
        for (int kk = 0; kk < 32; kk += 8) {
            unsigned a[4][4], b[4][2];
#pragma unroll
            for (int mi = 0; mi < 4; mi++) {
                int r = wm + mi * 16 + g;
                a[mi][0] = As[r][kk + tg];
                a[mi][1] = As[r + 8][kk + tg];
                a[mi][2] = As[r][kk + tg + 4];
                a[mi][3] = As[r + 8][kk + tg + 4];
            }
#pragma unroll
            for (int ni = 0; ni < 4; ni++) {
                int cc = wn + ni * 8 + g;
                b[ni][0] = Bs[kk + tg][cc];
                b[ni][1] = Bs[kk + tg + 4][cc];
            }
#pragma unroll
            for (int mi = 0; mi < 4; mi++)
#pragma unroll
                for (int ni = 0; ni < 4; ni++)
                    mma_tf32(c[mi * 4 + ni], a[mi], b[ni]);
        }
        __syncthreads();
    }

    // ---- epilogue ----
#pragma unroll
    for (int mi = 0; mi < 4; mi++) {
#pragma unroll
        for (int half = 0; half < 2; half++) {
            int row = m0 + wm + mi * 16 + g + half * 8;
            if (row >= cnt) continue;
            if (FIRST) {
#pragma unroll
                for (int ni = 0; ni < 4; ni++) {
                    int col = n0 + wn + ni * 8 + 2 * tg;
                    float v0 = c[mi * 4 + ni][half * 2 + 0] + bias[e * D_MODEL + col];
                    float v1 = c[mi * 4 + ni][half * 2 + 1] + bias[e * D_MODEL + col + 1];
                    v0 = fmaxf(v0, 0.f);
                    v1 = fmaxf(v1, 0.f);
                    float2* dst = (float2*)(g_H + ((size_t)e * CAP + row) * D_MODEL + col);
                    *dst = make_float2(v0, v1);
                }
            } else {
                float w  = g_wgt[e * CAP + row];
                int  tok = g_tok[e * CAP + row];
                float* orow = out + (size_t)tok * D_MODEL;
#pragma unroll
                for (int ni = 0; ni < 4; ni++) {
                    int col = n0 + wn + ni * 8 + 2 * tg;
                    float v0 = (c[mi * 4 + ni][half * 2 + 0] + bias[e * D_MODEL + col]) * w;
                    float v1 = (c[mi * 4 + ni][half * 2 + 1] + bias[e * D_MODEL + col + 1]) * w;
                    atomicAdd(orow + col, v0);
                    atomicAdd(orow + col + 1, v1);
                }
            }
        }
    }
}

// ---------------- launch ----------------
extern "C" void kernel_launch(void* const* d_in, const int* in_sizes, int n_in,
                              void* d_out, int out_size) {
    const float* x  = (const float*)d_in[0];
    const float* Wg = (const float*)d_in[1];
    const float* bg = (const float*)d_in[2];
    const float* W1 = (const float*)d_in[3];
    const float* b1 = (const float*)d_in[4];
    const float* W2 = (const float*)d_in[5];
    const float* b2 = (const float*)d_in[6];
    float* out = (float*)d_out;

    cudaMemsetAsync(out, 0, (size_t)out_size * sizeof(float));
    zero_cnt_kernel<<<1, 32>>>();
    gate_kernel<<<N_TOK / 8, 256>>>(x, Wg, bg);

    dim3 grid(D_MODEL / 128, CAP / 128, N_EXP);   // (n-tiles, m-tiles, expert)
    moe_gemm_kernel<true><<<grid, 256>>>(x, W1, b1, nullptr);
    moe_gemm_kernel<false><<<grid, 256>>>(x, W2, b2, out);
}

// round 5
// speedup vs baseline: 1.1914x; 1.1914x over previous
#include <cuda_runtime.h>
#include <cstdint>

#define D_MODEL 1024
#define N_EXP   8
#define N_TOK   8192
#define CAP     8192
#define MB_MAX  64            // max 128-row m-blocks per expert
#define BM      128
#define BN      128
#define BK      32
#define KTILES  32

// ---------------- device scratch (no allocation allowed) ----------------
__device__ int   g_cnt[N_EXP];
__device__ int   g_tok[N_EXP * CAP];
__device__ float g_wgt[N_EXP * CAP];
// permuted+rounded A tiles: [e][mb][kt][4096 floats]  (fragment order)
__device__ float g_A1[(size_t)N_EXP * MB_MAX * KTILES * 4096];
__device__ float g_A2[(size_t)N_EXP * MB_MAX * KTILES * 4096];
// permuted+rounded weights: [e][nb(8)][kt][4096 floats]
__device__ float g_W1p[(size_t)N_EXP * 8 * KTILES * 4096];
__device__ float g_W2p[(size_t)N_EXP * 8 * KTILES * 4096];

// ---------------- helpers ----------------
__device__ __forceinline__ uint32_t smem_u32(const void* p) {
    uint32_t a;
    asm("{ .reg .u64 t; cvta.to.shared.u64 t, %1; cvt.u32.u64 %0, t; }" : "=r"(a) : "l"(p));
    return a;
}
__device__ __forceinline__ unsigned f2tf32(float f) {
    unsigned r; asm("cvt.rna.tf32.f32 %0, %1;" : "=r"(r) : "f"(f)); return r;
}
__device__ __forceinline__ void mma_tf32(float* c, const uint32_t* a, const uint32_t* b) {
    asm volatile(
        "mma.sync.aligned.m16n8k8.row.col.f32.tf32.tf32.f32 "
        "{%0,%1,%2,%3}, {%4,%5,%6,%7}, {%8,%9}, {%0,%1,%2,%3};"
        : "+f"(c[0]), "+f"(c[1]), "+f"(c[2]), "+f"(c[3])
        : "r"(a[0]), "r"(a[1]), "r"(a[2]), "r"(a[3]),
          "r"(b[0]), "r"(b[1]));
}
#define CP_ASYNC16(dst, src) \
    asm volatile("cp.async.cg.shared.global [%0], [%1], 16;" :: "r"(dst), "l"(src))
#define CP_COMMIT()  asm volatile("cp.async.commit_group;" ::: "memory")
#define CP_WAIT1()   asm volatile("cp.async.wait_group 1;" ::: "memory")
#define LDS128(r, a) \
    asm volatile("ld.shared.v4.b32 {%0,%1,%2,%3}, [%4];" \
        : "=r"((r)[0]), "=r"((r)[1]), "=r"((r)[2]), "=r"((r)[3]) : "r"(a))
#define LDS64(r, a) \
    asm volatile("ld.shared.v2.b32 {%0,%1}, [%2];" \
        : "=r"((r)[0]), "=r"((r)[1]) : "r"(a))

// A fragment slot for element (r in 0..127, k in 0..31)
__device__ __forceinline__ int a_fidx(int r, int k) {
    return (((r >> 4) * 4 + (k >> 3)) << 7) + (((r & 7) * 4 + (k & 3)) << 2) +
           ((r >> 3) & 1) + 2 * ((k >> 2) & 1);
}
// B fragment slot for element (n in 0..127, k in 0..31)
__device__ __forceinline__ int b_fidx(int n, int k) {
    return (((n >> 3) * 4 + (k >> 3)) << 6) + (((n & 7) * 4 + (k & 3)) << 1) +
           ((k >> 2) & 1);
}

// ---------------- kernel: reset counters ----------------
__global__ void zero_cnt_kernel() {
    if (threadIdx.x < N_EXP) g_cnt[threadIdx.x] = 0;
}

// ---------------- kernel: gating + top-2 ----------------
__global__ void gate_kernel(const float* __restrict__ x,
                            const float* __restrict__ Wg,
                            const float* __restrict__ bg) {
    int tok  = blockIdx.x * 8 + (threadIdx.x >> 5);
    int lane = threadIdx.x & 31;
    if (tok >= N_TOK) return;
    const float* xr = x + (size_t)tok * D_MODEL;

    float s[8];
#pragma unroll
    for (int e = 0; e < 8; e++) s[e] = 0.f;
    for (int k = lane; k < D_MODEL; k += 32) {
        float xv = xr[k];
        const float4* wr = (const float4*)(Wg + (size_t)k * N_EXP);
        float4 w0 = wr[0], w1 = wr[1];
        s[0] += xv * w0.x; s[1] += xv * w0.y; s[2] += xv * w0.z; s[3] += xv * w0.w;
        s[4] += xv * w1.x; s[5] += xv * w1.y; s[6] += xv * w1.z; s[7] += xv * w1.w;
    }
#pragma unroll
    for (int e = 0; e < 8; e++)
#pragma unroll
        for (int off = 16; off > 0; off >>= 1)
            s[e] += __shfl_xor_sync(0xffffffffu, s[e], off);

    if (lane == 0) {
        float best = -3.4e38f, best2 = -3.4e38f;
        int e0 = 0, e1 = 0;
#pragma unroll
        for (int e = 0; e < 8; e++) {
            float v = s[e] + bg[e];
            if (v > best)       { best2 = best; e1 = e0; best = v; e0 = e; }
            else if (v > best2) { best2 = v; e1 = e; }
        }
        int p0 = atomicAdd(&g_cnt[e0], 1);
        g_tok[e0 * CAP + p0] = tok;
        g_wgt[e0 * CAP + p0] = best;
        int p1 = atomicAdd(&g_cnt[e1], 1);
        g_tok[e1 * CAP + p1] = tok;
        g_wgt[e1 * CAP + p1] = best2;
    }
}

// ---------------- kernel: weight permute+round ----------------
// src W[e][k][n] (row-major) -> g_Wp[e][nb][kt][fragment-permuted 4096]
// NOTE: destination selected IN DEVICE CODE (host cannot take &__device__ sym)
__global__ void w_perm_kernel(const float* __restrict__ W, int which) {
    __shared__ float stg[4096];
    float* dst = which ? g_W2p : g_W1p;
    const int kt = blockIdx.x, nb = blockIdx.y, e = blockIdx.z;
    const int tid = threadIdx.x;
    const int kr  = tid >> 3;          // 0..31 (k within tile)
    const int nc8 = tid & 7;           // column group
    const float* Ws = W + (size_t)e * D_MODEL * D_MODEL;
#pragma unroll
    for (int i = 0; i < 4; i++) {
        int n_in = nc8 * 16 + i * 4;
        float4 v = *(const float4*)(Ws + (size_t)(kt * 32 + kr) * D_MODEL + nb * 128 + n_in);
        stg[b_fidx(n_in + 0, kr)] = __uint_as_float(f2tf32(v.x));
        stg[b_fidx(n_in + 1, kr)] = __uint_as_float(f2tf32(v.y));
        stg[b_fidx(n_in + 2, kr)] = __uint_as_float(f2tf32(v.z));
        stg[b_fidx(n_in + 3, kr)] = __uint_as_float(f2tf32(v.w));
    }
    __syncthreads();
    float4* d4 = (float4*)(dst + ((size_t)(e * 8 + nb) * KTILES + kt) * 4096);
    const float4* s4 = (const float4*)stg;
#pragma unroll
    for (int i = 0; i < 4; i++) d4[tid + i * 256] = s4[tid + i * 256];
}

// ---------------- kernel: gather + round + permute X -> g_A1 ----------------
__global__ void a1_perm_kernel(const float* __restrict__ x) {
    __shared__ float stg[4096];
    const int mb = blockIdx.x, e = blockIdx.y;
    const int cnt = g_cnt[e];
    if (mb * BM >= cnt) return;
    const int tid = threadIdx.x;
    const int r    = tid >> 1;         // 0..127
    const int half = tid & 1;
    int ai  = mb * BM + r;
    int tok = (ai < cnt) ? g_tok[e * CAP + ai] : g_tok[e * CAP];
    const float* src = x + (size_t)tok * D_MODEL;
    float* dstb = g_A1 + (size_t)(e * MB_MAX + mb) * KTILES * 4096;

    for (int kt = 0; kt < KTILES; kt++) {
#pragma unroll
        for (int i = 0; i < 4; i++) {
            int k_in = half * 16 + i * 4;
            float4 v = *(const float4*)(src + kt * 32 + k_in);
            stg[a_fidx(r, k_in + 0)] = __uint_as_float(f2tf32(v.x));
            stg[a_fidx(r, k_in + 1)] = __uint_as_float(f2tf32(v.y));
            stg[a_fidx(r, k_in + 2)] = __uint_as_float(f2tf32(v.z));
            stg[a_fidx(r, k_in + 3)] = __uint_as_float(f2tf32(v.w));
        }
        __syncthreads();
        float4* d4 = (float4*)(dstb + (size_t)kt * 4096);
        const float4* s4 = (const float4*)stg;
#pragma unroll
        for (int i = 0; i < 4; i++) d4[tid + i * 256] = s4[tid + i * 256];
        __syncthreads();
    }
}

// ---------------- kernel: grouped GEMM (mma.sync tf32, cp.async 2-stage) ----
// FIRST: D = relu(A1 @ W1^T + b1) -> g_A2 (permuted, rounded)
// else : out[tok] += w * (A2 @ W2^T + b2)
template <bool FIRST>
__global__ void __launch_bounds__(256, 2)
moe_gemm(const float* __restrict__ bias, float* __restrict__ out) {
    const int e   = blockIdx.z;
    const int cnt = g_cnt[e];
    const int mb  = blockIdx.y;
    if (mb * BM >= cnt) return;
    const int nb  = blockIdx.x;

    extern __shared__ __align__(128) char smem[];   // 2 stages x (A 16K + B 16K)
    const uint32_t sb = smem_u32(smem);
    const int tid  = threadIdx.x;
    const int lane = tid & 31;
    const int warp = tid >> 5;
    const int wm   = warp >> 2;          // 0..1
    const int wn   = warp & 3;           // 0..3
    const int g    = lane >> 2;
    const int tg   = lane & 3;

    const float* Asrc = (FIRST ? g_A1 : g_A2) + (size_t)(e * MB_MAX + mb) * KTILES * 4096;
    const float* Bsrc = (FIRST ? g_W1p : g_W2p) + (size_t)(e * 8 + nb) * KTILES * 4096;

    float c[16][4];
#pragma unroll
    for (int i = 0; i < 16; i++)
#pragma unroll
        for (int j = 0; j < 4; j++) c[i][j] = 0.f;

    // stage loader: tile kt -> stage s (pure linear copies)
    auto load_stage = [&](int kt, int s) {
        uint32_t da = sb + s * 32768 + tid * 16;
        const float* sa = Asrc + (size_t)kt * 4096 + tid * 4;
        const float* sw = Bsrc + (size_t)kt * 4096 + tid * 4;
#pragma unroll
        for (int cc = 0; cc < 4; cc++) {
            CP_ASYNC16(da + cc * 4096,         sa + cc * 1024);
            CP_ASYNC16(da + 16384 + cc * 4096, sw + cc * 1024);
        }
    };

    load_stage(0, 0); CP_COMMIT();
    load_stage(1, 1); CP_COMMIT();

    const uint32_t aoff = wm * 8192 + lane * 16;          // A frag base (bytes)
    const uint32_t boff = 16384 + wn * 4096 + lane * 8;   // B frag base (bytes)

    for (int it = 0; it < KTILES; it++) {
        CP_WAIT1();
        __syncthreads();
        const uint32_t st = sb + (it & 1) * 32768;
#pragma unroll
        for (int kk = 0; kk < 4; kk++) {
            uint32_t a[4][4], b[4][2];
#pragma unroll
            for (int mi = 0; mi < 4; mi++)
                LDS128(a[mi], st + aoff + mi * 2048 + kk * 512);
#pragma unroll
            for (int ni = 0; ni < 4; ni++)
                LDS64(b[ni], st + boff + ni * 1024 + kk * 256);
#pragma unroll
            for (int mi = 0; mi < 4; mi++)
#pragma unroll
                for (int ni = 0; ni < 4; ni++)
                    mma_tf32(c[mi * 4 + ni], a[mi], b[ni]);
        }
        __syncthreads();
        if (it + 2 < KTILES) load_stage(it + 2, it & 1);
        CP_COMMIT();
    }

    // ---- epilogue ----
    const float* brow = bias + e * D_MODEL;
#pragma unroll
    for (int mi = 0; mi < 4; mi++) {
#pragma unroll
        for (int ni = 0; ni < 4; ni++) {
#pragma unroll
            for (int j = 0; j < 4; j++) {
                int r_blk = wm * 64 + mi * 16 + g + 8 * (j >> 1);
                int grow  = mb * BM + r_blk;
                if (grow >= cnt) continue;
                int n_blk  = wn * 32 + ni * 8 + 2 * tg + (j & 1);
                int n_glob = nb * BN + n_blk;
                float v = c[mi * 4 + ni][j] + __ldg(brow + n_glob);
                if (FIRST) {
                    v = fmaxf(v, 0.f);
                    int kt = n_glob >> 5, k_in = n_glob & 31;
                    g_A2[((size_t)(e * MB_MAX + mb) * KTILES + kt) * 4096 +
                         a_fidx(r_blk, k_in)] = __uint_as_float(f2tf32(v));
                } else {
                    float w = g_wgt[e * CAP + grow];
                    atomicAdd(out + (size_t)g_tok[e * CAP + grow] * D_MODEL + n_glob,
                              v * w);
                }
            }
        }
    }
}

// ---------------- launch ----------------
extern "C" void kernel_launch(void* const* d_in, const int* in_sizes, int n_in,
                              void* d_out, int out_size) {
    const float* x  = (const float*)d_in[0];
    const float* Wg = (const float*)d_in[1];
    const float* bg = (const float*)d_in[2];
    const float* W1 = (const float*)d_in[3];
    const float* b1 = (const float*)d_in[4];
    const float* W2 = (const float*)d_in[5];
    const float* b2 = (const float*)d_in[6];
    float* out = (float*)d_out;

    cudaFuncSetAttribute(moe_gemm<true>,
                         cudaFuncAttributeMaxDynamicSharedMemorySize, 65536);
    cudaFuncSetAttribute(moe_gemm<false>,
                         cudaFuncAttributeMaxDynamicSharedMemorySize, 65536);

    cudaMemsetAsync(out, 0, (size_t)out_size * sizeof(float));
    zero_cnt_kernel<<<1, 32>>>();
    gate_kernel<<<N_TOK / 8, 256>>>(x, Wg, bg);

    dim3 wg(KTILES, 8, N_EXP);
    w_perm_kernel<<<wg, 256>>>(W1, 0);
    w_perm_kernel<<<wg, 256>>>(W2, 1);
    a1_perm_kernel<<<dim3(MB_MAX, N_EXP), 256>>>(x);

    dim3 grid(D_MODEL / BN, MB_MAX, N_EXP);   // (8, 64, 8)
    moe_gemm<true><<<grid, 256, 65536>>>(b1, nullptr);
    moe_gemm<false><<<grid, 256, 65536>>>(b2, out);
}